// round 2
// baseline (speedup 1.0000x reference)
#include <cuda_runtime.h>

// EdgeModel: out = relu(concat(src,dst,ea,u[batch]) @ W1.T + b1) @ W2.T + b2
// E edges, IN_NF=112, HID=64, OUT_NF=32. fp32 throughout, FFMA2 (f32x2) inner loops.
// batch indices read as int32 (harness materializes index arrays as int32).

#define THREADS   256
#define TILE_E    128
#define IN_NF     112
#define HID       64
#define OUT_NF    32
#define XS_STRIDE 114   // even (f32x2 pairs), tx*114 mod 32 = tx*18 -> 16 distinct banks
#define W1_STRIDE 114
#define HS_STRIDE 66
#define OS_STRIDE 33

// packed fp32x2 FMA: (a0*b0+c0, a1*b1+c1)
__device__ __forceinline__ unsigned long long fma2(unsigned long long a,
                                                   unsigned long long b,
                                                   unsigned long long c) {
    unsigned long long d;
    asm("fma.rn.f32x2 %0, %1, %2, %3;" : "=l"(d) : "l"(a), "l"(b), "l"(c));
    return d;
}

__device__ __forceinline__ float acc_sum(unsigned long long a) {
    float lo = __uint_as_float((unsigned int)a);
    float hi = __uint_as_float((unsigned int)(a >> 32));
    return lo + hi;
}

extern "C" __global__ void __launch_bounds__(THREADS, 1)
edge_mlp_kernel(const float* __restrict__ src, const float* __restrict__ dst,
                const float* __restrict__ ea, const float* __restrict__ u,
                const int* __restrict__ batch,
                const float* __restrict__ W1, const float* __restrict__ b1,
                const float* __restrict__ W2, const float* __restrict__ b2,
                float* __restrict__ out, int E)
{
    extern __shared__ float sm[];
    float* xs  = sm;                          // [TILE_E][XS_STRIDE], aliased later by os
    float* hs  = xs + TILE_E * XS_STRIDE;     // [TILE_E][HS_STRIDE]
    float* ws1 = hs + TILE_E * HS_STRIDE;     // [64][W1_STRIDE]
    float* ws2 = ws1 + HID * W1_STRIDE;       // [32][64]
    float* b1s = ws2 + OUT_NF * HID;          // [64]
    float* b2s = b1s + HID;                   // [32]

    const int t  = threadIdx.x;
    const int e0 = blockIdx.x * TILE_E;

    // ---- stage weights into smem ----
    for (int i = t; i < HID * IN_NF; i += THREADS) {
        int j = i / IN_NF, k = i % IN_NF;
        ws1[j * W1_STRIDE + k] = W1[i];
    }
    for (int i = t; i < OUT_NF * HID; i += THREADS) ws2[i] = W2[i];
    if (t < HID)    b1s[t] = b1[t];
    if (t < OUT_NF) b2s[t] = b2[t];

    // ---- stage x tile: [TILE_E][112] = [src|dst|ea|u[batch]] as float2 ----
    const float2* src2 = (const float2*)src;
    const float2* dst2 = (const float2*)dst;
    const float2* ea2  = (const float2*)ea;
    const float2* u2   = (const float2*)u;
    #pragma unroll
    for (int it = 0; it < (TILE_E * 56) / THREADS; ++it) {
        int idx = t + it * THREADS;
        int el  = idx / 56;
        int c   = idx % 56;
        int e   = e0 + el;
        float2 v = make_float2(0.f, 0.f);
        if (e < E) {
            if (c < 16)       v = src2[(size_t)e * 16 + c];
            else if (c < 32)  v = dst2[(size_t)e * 16 + (c - 16)];
            else if (c < 48)  v = ea2[(size_t)e * 16 + (c - 32)];
            else {
                int bi = batch[e];
                v = u2[(size_t)bi * 8 + (c - 48)];
            }
        }
        *(float2*)&xs[el * XS_STRIDE + c * 2] = v;
    }
    __syncthreads();

    const int tx = t & 15;   // edge group: edges tx + 16*i
    const int ty = t >> 4;   // 0..15

    // ================= GEMM1: [128 x 112] @ [112 x 64] =================
    {
        const unsigned long long* xs2  = (const unsigned long long*)xs;
        const unsigned long long* ws12 = (const unsigned long long*)ws1;
        const int jb = ty * 4;

        unsigned long long acc[8][4];
        #pragma unroll
        for (int i = 0; i < 8; ++i)
            #pragma unroll
            for (int j = 0; j < 4; ++j) acc[i][j] = 0ULL;

        int arow[8], brow[4];
        #pragma unroll
        for (int i = 0; i < 8; ++i) arow[i] = ((tx + 16 * i) * XS_STRIDE) >> 1;
        #pragma unroll
        for (int j = 0; j < 4; ++j) brow[j] = ((jb + j) * W1_STRIDE) >> 1;

        #pragma unroll 4
        for (int k2 = 0; k2 < IN_NF / 2; ++k2) {
            unsigned long long bv[4], av[8];
            #pragma unroll
            for (int j = 0; j < 4; ++j) bv[j] = ws12[brow[j] + k2];
            #pragma unroll
            for (int i = 0; i < 8; ++i) av[i] = xs2[arow[i] + k2];
            #pragma unroll
            for (int i = 0; i < 8; ++i)
                #pragma unroll
                for (int j = 0; j < 4; ++j)
                    acc[i][j] = fma2(av[i], bv[j], acc[i][j]);
        }

        // epilogue: bias + relu -> hs
        #pragma unroll
        for (int i = 0; i < 8; ++i) {
            int el = tx + 16 * i;
            #pragma unroll
            for (int j = 0; j < 4; ++j) {
                float h = acc_sum(acc[i][j]) + b1s[jb + j];
                hs[el * HS_STRIDE + jb + j] = fmaxf(h, 0.f);
            }
        }
    }
    __syncthreads();

    // ================= GEMM2: [128 x 64] @ [64 x 32] =================
    float oreg[8][2];
    {
        const unsigned long long* hs2  = (const unsigned long long*)hs;
        const unsigned long long* ws22 = (const unsigned long long*)ws2;
        const int nb = ty * 2;

        unsigned long long acc[8][2];
        #pragma unroll
        for (int i = 0; i < 8; ++i)
            #pragma unroll
            for (int j = 0; j < 2; ++j) acc[i][j] = 0ULL;

        int arow[8], brow[2];
        #pragma unroll
        for (int i = 0; i < 8; ++i) arow[i] = ((tx + 16 * i) * HS_STRIDE) >> 1;
        #pragma unroll
        for (int j = 0; j < 2; ++j) brow[j] = ((nb + j) * HID) >> 1;

        #pragma unroll 4
        for (int k2 = 0; k2 < HID / 2; ++k2) {
            unsigned long long bv[2], av[8];
            #pragma unroll
            for (int j = 0; j < 2; ++j) bv[j] = ws22[brow[j] + k2];
            #pragma unroll
            for (int i = 0; i < 8; ++i) av[i] = hs2[arow[i] + k2];
            #pragma unroll
            for (int i = 0; i < 8; ++i)
                #pragma unroll
                for (int j = 0; j < 2; ++j)
                    acc[i][j] = fma2(av[i], bv[j], acc[i][j]);
        }
        #pragma unroll
        for (int i = 0; i < 8; ++i)
            #pragma unroll
            for (int j = 0; j < 2; ++j)
                oreg[i][j] = acc_sum(acc[i][j]) + b2s[nb + j];
    }
    __syncthreads();   // everyone done reading hs / xs before aliasing xs as os

    // ---- stage output tile to smem (os aliases xs), then coalesced store ----
    float* os = xs;
    {
        const int nb = ty * 2;
        #pragma unroll
        for (int i = 0; i < 8; ++i) {
            int el = tx + 16 * i;
            #pragma unroll
            for (int j = 0; j < 2; ++j)
                os[el * OS_STRIDE + nb + j] = oreg[i][j];
        }
    }
    __syncthreads();

    for (int idx = t; idx < TILE_E * OUT_NF; idx += THREADS) {
        int el = idx >> 5;
        int n  = idx & 31;
        int e  = e0 + el;
        if (e < E) out[(size_t)e * OUT_NF + n] = os[el * OS_STRIDE + n];
    }
}

extern "C" void kernel_launch(void* const* d_in, const int* in_sizes, int n_in,
                              void* d_out, int out_size) {
    const float* src   = (const float*)d_in[0];
    const float* dst   = (const float*)d_in[1];
    const float* ea    = (const float*)d_in[2];
    const float* u     = (const float*)d_in[3];
    const int*   batch = (const int*)d_in[4];
    const float* W1    = (const float*)d_in[5];
    const float* b1    = (const float*)d_in[6];
    const float* W2    = (const float*)d_in[7];
    const float* b2    = (const float*)d_in[8];
    float*       out   = (float*)d_out;

    int E = in_sizes[0] / 32;
    int grid = (E + TILE_E - 1) / TILE_E;

    size_t smem_floats = (size_t)TILE_E * XS_STRIDE + (size_t)TILE_E * HS_STRIDE +
                         (size_t)HID * W1_STRIDE + (size_t)OUT_NF * HID + HID + OUT_NF;
    size_t smem = smem_floats * sizeof(float);

    cudaFuncSetAttribute(edge_mlp_kernel,
                         cudaFuncAttributeMaxDynamicSharedMemorySize, (int)smem);
    edge_mlp_kernel<<<grid, THREADS, smem>>>(src, dst, ea, u, batch,
                                             W1, b1, W2, b2, out, E);
}

// round 4
// speedup vs baseline: 6.9336x; 6.9336x over previous
#include <cuda_runtime.h>
#include <cstdint>

#define THREADS 256
#define TILE    128
#define TPC     4          // tiles per CTA
#define XS_S    132        // x stride (words), ≡4 mod 32 -> conflict-free A frags
#define HS_S    68         // h stride, ≡4 mod 32
#define W1_S    72         // W1 stride, ≡8 mod 32 -> conflict-free B frags
#define W2_S    40         // W2 stride, ≡8 mod 32

__device__ __forceinline__ float tf32r(float x) {
    float y; asm("cvt.rna.tf32.f32 %0, %1;" : "=f"(y) : "f"(x)); return y;
}
__device__ __forceinline__ float4 tf32r4(float4 v) {
    v.x = tf32r(v.x); v.y = tf32r(v.y); v.z = tf32r(v.z); v.w = tf32r(v.w); return v;
}

__device__ __forceinline__ void mma_tf32(float* d, const uint32_t* a, const uint32_t* b) {
    asm volatile(
        "mma.sync.aligned.m16n8k8.row.col.f32.tf32.tf32.f32 "
        "{%0,%1,%2,%3}, {%4,%5,%6,%7}, {%8,%9}, {%0,%1,%2,%3};"
        : "+f"(d[0]), "+f"(d[1]), "+f"(d[2]), "+f"(d[3])
        : "r"(a[0]), "r"(a[1]), "r"(a[2]), "r"(a[3]), "r"(b[0]), "r"(b[1]));
}

// smem floats: xs 128*132=16896 (h aliases), w1 112*72=8064, w2 64*40=2560, b 96
#define SM_FLOATS (128 * XS_S + 112 * W1_S + 64 * W2_S + 64 + 32)

extern "C" __global__ void __launch_bounds__(THREADS, 2)
edge_mlp_mma(const float* __restrict__ src, const float* __restrict__ dst,
             const float* __restrict__ ea, const float* __restrict__ u,
             const int* __restrict__ batch,
             const float* __restrict__ W1, const float* __restrict__ b1,
             const float* __restrict__ W2, const float* __restrict__ b2,
             float* __restrict__ out, int E, int ntiles)
{
    extern __shared__ float smf[];
    float* xs  = smf;                     // [128][XS_S], later aliased by h [128][HS_S]
    float* w1s = xs + 128 * XS_S;         // [112][W1_S]  (W1 transposed: [k][n])
    float* w2s = w1s + 112 * W1_S;        // [64][W2_S]   (W2 transposed: [k][n])
    float* b1s = w2s + 64 * W2_S;         // 64
    float* b2s = b1s + 64;                // 32

    const int t    = threadIdx.x;
    const int w    = t >> 5;
    const int lane = t & 31;
    const int gid  = lane >> 2;   // 0..7
    const int ctid = lane & 3;    // 0..3
    const int mbase = (w & 3) * 32;
    const int nbase = (w >> 2) * 32;   // GEMM1 N
    const int nb2   = (w >> 2) * 16;   // GEMM2 N

    // ---- stage weights (transposed, tf32-rounded) ----
    for (int i = t; i < 64 * 112; i += THREADS) {
        int n = i / 112, k = i % 112;
        w1s[k * W1_S + n] = tf32r(W1[i]);
    }
    for (int i = t; i < 32 * 64; i += THREADS) {
        int n = i / 64, k = i % 64;
        w2s[k * W2_S + n] = tf32r(W2[i]);
    }
    if (t < 64) b1s[t] = b1[t];
    if (t < 32) b2s[t] = b2[t];

    for (int j = 0; j < TPC; j++) {
        const int tile = blockIdx.x * TPC + j;
        if (tile >= ntiles) break;
        const int e0 = tile * TILE;

        // ---- stage x tile: [128][112] = [src|dst|ea|u[batch]], tf32-rounded ----
        {
            #pragma unroll
            for (int blk = 0; blk < 3; blk++) {
                const float4* a4 = (blk == 0) ? (const float4*)src
                                 : (blk == 1) ? (const float4*)dst
                                              : (const float4*)ea;
                #pragma unroll
                for (int it = 0; it < 4; it++) {
                    int r = (t >> 3) + 32 * it, c = t & 7;
                    int e = e0 + r;
                    float4 v = make_float4(0.f, 0.f, 0.f, 0.f);
                    if (e < E) v = a4[(size_t)e * 8 + c];
                    *(float4*)&xs[r * XS_S + blk * 32 + c * 4] = tf32r4(v);
                }
            }
            const float4* u4 = (const float4*)u;
            #pragma unroll
            for (int it = 0; it < 2; it++) {
                int r = (t >> 2) + 64 * it, c = t & 3;
                int e = e0 + r;
                float4 v = make_float4(0.f, 0.f, 0.f, 0.f);
                if (e < E) { int bi = batch[e]; v = u4[(size_t)bi * 4 + c]; }
                *(float4*)&xs[r * XS_S + 96 + c * 4] = tf32r4(v);
            }
        }
        __syncthreads();

        // ================= GEMM1: [128x112] @ [112x64] (tf32 mma) =================
        float acc[2][4][4];
        #pragma unroll
        for (int mt = 0; mt < 2; mt++)
            #pragma unroll
            for (int nt = 0; nt < 4; nt++)
                #pragma unroll
                for (int q = 0; q < 4; q++) acc[mt][nt][q] = 0.f;

        {
            const uint32_t* xsu = (const uint32_t*)xs;
            const uint32_t* w1u = (const uint32_t*)w1s;
            const int arow = (mbase + gid) * XS_S + ctid;
            const int brow = ctid * W1_S + nbase + gid;

            #pragma unroll
            for (int ks = 0; ks < 14; ks++) {
                uint32_t a[2][4], b[4][2];
                #pragma unroll
                for (int mt = 0; mt < 2; mt++) {
                    int base = arow + mt * 16 * XS_S + ks * 8;
                    a[mt][0] = xsu[base];
                    a[mt][1] = xsu[base + 8 * XS_S];
                    a[mt][2] = xsu[base + 4];
                    a[mt][3] = xsu[base + 8 * XS_S + 4];
                }
                #pragma unroll
                for (int nt = 0; nt < 4; nt++) {
                    int base = brow + ks * 8 * W1_S + nt * 8;
                    b[nt][0] = w1u[base];
                    b[nt][1] = w1u[base + 4 * W1_S];
                }
                #pragma unroll
                for (int mt = 0; mt < 2; mt++)
                    #pragma unroll
                    for (int nt = 0; nt < 4; nt++)
                        mma_tf32(acc[mt][nt], a[mt], b[nt]);
            }
        }
        __syncthreads();   // all warps done reading xs before h overwrites it

        // ---- epilogue 1: bias + relu + tf32 round -> h (aliases xs) ----
        float* h = xs;     // [128][HS_S]
        #pragma unroll
        for (int mt = 0; mt < 2; mt++) {
            int r0 = mbase + 16 * mt + gid;
            #pragma unroll
            for (int nt = 0; nt < 4; nt++) {
                int c = nbase + 8 * nt + 2 * ctid;
                float2 v0, v1;
                v0.x = tf32r(fmaxf(acc[mt][nt][0] + b1s[c],     0.f));
                v0.y = tf32r(fmaxf(acc[mt][nt][1] + b1s[c + 1], 0.f));
                v1.x = tf32r(fmaxf(acc[mt][nt][2] + b1s[c],     0.f));
                v1.y = tf32r(fmaxf(acc[mt][nt][3] + b1s[c + 1], 0.f));
                *(float2*)&h[r0 * HS_S + c]       = v0;
                *(float2*)&h[(r0 + 8) * HS_S + c] = v1;
            }
        }
        __syncthreads();

        // ================= GEMM2: [128x64] @ [64x32] (tf32 mma) =================
        float acc2[2][2][4];
        #pragma unroll
        for (int mt = 0; mt < 2; mt++)
            #pragma unroll
            for (int nt = 0; nt < 2; nt++)
                #pragma unroll
                for (int q = 0; q < 4; q++) acc2[mt][nt][q] = 0.f;

        {
            const uint32_t* hu  = (const uint32_t*)h;
            const uint32_t* w2u = (const uint32_t*)w2s;
            const int arow = (mbase + gid) * HS_S + ctid;
            const int brow = ctid * W2_S + nb2 + gid;

            #pragma unroll
            for (int ks = 0; ks < 8; ks++) {
                uint32_t a[2][4], b[2][2];
                #pragma unroll
                for (int mt = 0; mt < 2; mt++) {
                    int base = arow + mt * 16 * HS_S + ks * 8;
                    a[mt][0] = hu[base];
                    a[mt][1] = hu[base + 8 * HS_S];
                    a[mt][2] = hu[base + 4];
                    a[mt][3] = hu[base + 8 * HS_S + 4];
                }
                #pragma unroll
                for (int nt = 0; nt < 2; nt++) {
                    int base = brow + ks * 8 * W2_S + nt * 8;
                    b[nt][0] = w2u[base];
                    b[nt][1] = w2u[base + 4 * W2_S];
                }
                #pragma unroll
                for (int mt = 0; mt < 2; mt++)
                    #pragma unroll
                    for (int nt = 0; nt < 2; nt++)
                        mma_tf32(acc2[mt][nt], a[mt], b[nt]);
            }
        }

        // ---- epilogue 2: bias + store directly to gmem ----
        #pragma unroll
        for (int mt = 0; mt < 2; mt++) {
            int r0 = mbase + 16 * mt + gid;
            #pragma unroll
            for (int nt = 0; nt < 2; nt++) {
                int c = nb2 + 8 * nt + 2 * ctid;
                int e = e0 + r0;
                if (e < E) {
                    float2 v;
                    v.x = acc2[mt][nt][0] + b2s[c];
                    v.y = acc2[mt][nt][1] + b2s[c + 1];
                    *(float2*)&out[(size_t)e * 32 + c] = v;
                }
                if (e + 8 < E) {
                    float2 v;
                    v.x = acc2[mt][nt][2] + b2s[c];
                    v.y = acc2[mt][nt][3] + b2s[c + 1];
                    *(float2*)&out[(size_t)(e + 8) * 32 + c] = v;
                }
            }
        }
        __syncthreads();   // before next tile's staging overwrites xs/h
    }
}

extern "C" void kernel_launch(void* const* d_in, const int* in_sizes, int n_in,
                              void* d_out, int out_size) {
    const float* src   = (const float*)d_in[0];
    const float* dst   = (const float*)d_in[1];
    const float* ea    = (const float*)d_in[2];
    const float* u     = (const float*)d_in[3];
    const int*   batch = (const int*)d_in[4];
    const float* W1    = (const float*)d_in[5];
    const float* b1    = (const float*)d_in[6];
    const float* W2    = (const float*)d_in[7];
    const float* b2    = (const float*)d_in[8];
    float*       out   = (float*)d_out;

    int E = in_sizes[0] / 32;
    int ntiles = (E + TILE - 1) / TILE;
    int grid = (ntiles + TPC - 1) / TPC;

    size_t smem = SM_FLOATS * sizeof(float);
    cudaFuncSetAttribute(edge_mlp_mma,
                         cudaFuncAttributeMaxDynamicSharedMemorySize, (int)smem);
    edge_mlp_mma<<<grid, THREADS, smem>>>(src, dst, ea, u, batch,
                                          W1, b1, W2, b2, out, E, ntiles);
}

// round 5
// speedup vs baseline: 12.0040x; 1.7313x over previous
#include <cuda_runtime.h>
#include <cuda_fp16.h>
#include <cstdint>

#define THREADS 256
#define TPC     4        // tiles per CTA
#define TILE    128
#define XS_H    120      // xs stride in halves (word-stride 60 ≡ 28 mod 32 -> conflict-free frags)
#define W1_H    120
#define HS_H    72       // h stride in halves (word-stride 36 ≡ 4 mod 32)

__device__ __forceinline__ uint2 f4_to_h4(float4 v) {
    __half2 lo = __floats2half2_rn(v.x, v.y);
    __half2 hi = __floats2half2_rn(v.z, v.w);
    uint2 r;
    r.x = *(uint32_t*)&lo;
    r.y = *(uint32_t*)&hi;
    return r;
}
__device__ __forceinline__ uint32_t f2_to_h2(float x, float y) {
    __half2 h = __floats2half2_rn(x, y);
    return *(uint32_t*)&h;
}

__device__ __forceinline__ void mma_f16(float* d, const uint32_t* a, const uint32_t* b) {
    asm volatile(
        "mma.sync.aligned.m16n8k16.row.col.f32.f16.f16.f32 "
        "{%0,%1,%2,%3}, {%4,%5,%6,%7}, {%8,%9}, {%0,%1,%2,%3};"
        : "+f"(d[0]), "+f"(d[1]), "+f"(d[2]), "+f"(d[3])
        : "r"(a[0]), "r"(a[1]), "r"(a[2]), "r"(a[3]), "r"(b[0]), "r"(b[1]));
}

// smem (halves): xs 128*120=15360 (h [128][72] aliases), w1 64*120=7680; fp32: b1 64, b2 32
#define SM_BYTES ((128 * XS_H + 64 * W1_H) * 2 + (64 + 32) * 4)

extern "C" __global__ void __launch_bounds__(THREADS, 2)
edge_mlp_h(const float* __restrict__ src, const float* __restrict__ dst,
           const float* __restrict__ ea, const float* __restrict__ u,
           const int* __restrict__ batch,
           const float* __restrict__ W1, const float* __restrict__ b1,
           const float* __restrict__ W2, const float* __restrict__ b2,
           float* __restrict__ out, int E, int ntiles)
{
    extern __shared__ char smraw[];
    __half* xs  = (__half*)smraw;                 // [128][XS_H], aliased by h [128][HS_H]
    __half* w1s = xs + 128 * XS_H;                // [64 n][W1_H k]
    float*  b1s = (float*)(w1s + 64 * W1_H);      // 64
    float*  b2s = b1s + 64;                       // 32

    const int t    = threadIdx.x;
    const int w    = t >> 5;
    const int lane = t & 31;
    const int gid  = lane >> 2;     // 0..7
    const int ctid = lane & 3;      // 0..3
    const int mbase = (w & 3) * 32;
    const int nbase = (w >> 2) * 32;   // GEMM1 N slice
    const int nb2   = (w >> 2) * 16;   // GEMM2 N slice

    // ---- stage W1 as [n][k] halves ----
    {
        const float2* w12 = (const float2*)W1;     // 64*56 float2
        #pragma unroll
        for (int it = 0; it < 14; it++) {
            int i = t + it * THREADS;              // 0..3583
            int n = i / 56, k2 = i % 56;
            float2 v = w12[i];
            *(uint32_t*)&w1s[n * W1_H + k2 * 2] = f2_to_h2(v.x, v.y);
        }
        if (t < 64) b1s[t] = b1[t];
        if (t < 32) b2s[t] = b2[t];
    }

    // ---- W2 fragments persist in registers (loaded once from gmem) ----
    uint32_t w2r[4][2][2];   // [ks][nt][b0/b1]
    #pragma unroll
    for (int ks = 0; ks < 4; ks++)
        #pragma unroll
        for (int nt = 0; nt < 2; nt++) {
            int n  = nb2 + 8 * nt + gid;
            int k0 = 16 * ks + 2 * ctid;
            float2 v0 = *(const float2*)&W2[n * 64 + k0];
            float2 v1 = *(const float2*)&W2[n * 64 + k0 + 8];
            w2r[ks][nt][0] = f2_to_h2(v0.x, v0.y);
            w2r[ks][nt][1] = f2_to_h2(v1.x, v1.y);
        }

    for (int j = 0; j < TPC; j++) {
        const int tile = blockIdx.x * TPC + j;
        if (tile >= ntiles) break;
        const int e0 = tile * TILE;

        // ---- stage x tile: [128][112] halves = [src|dst|ea|u[batch]] ----
        {
            #pragma unroll
            for (int blk = 0; blk < 3; blk++) {
                const float4* a4 = (blk == 0) ? (const float4*)src
                                 : (blk == 1) ? (const float4*)dst
                                              : (const float4*)ea;
                #pragma unroll
                for (int it = 0; it < 4; it++) {
                    int r = (t >> 3) + 32 * it, c = t & 7;
                    int e = e0 + r;
                    float4 v = make_float4(0.f, 0.f, 0.f, 0.f);
                    if (e < E) v = a4[(size_t)e * 8 + c];
                    *(uint2*)&xs[r * XS_H + blk * 32 + c * 4] = f4_to_h4(v);
                }
            }
            const float4* u4 = (const float4*)u;
            #pragma unroll
            for (int it = 0; it < 2; it++) {
                int r = (t >> 2) + 64 * it, c = t & 3;
                int e = e0 + r;
                float4 v = make_float4(0.f, 0.f, 0.f, 0.f);
                if (e < E) { int bi = batch[e]; v = u4[(size_t)bi * 4 + c]; }
                *(uint2*)&xs[r * XS_H + 96 + c * 4] = f4_to_h4(v);
            }
        }
        __syncthreads();

        // ================= GEMM1: [128x112] @ [112x64], fp16 mma =================
        float acc[2][4][4];
        #pragma unroll
        for (int mt = 0; mt < 2; mt++)
            #pragma unroll
            for (int nt = 0; nt < 4; nt++)
                #pragma unroll
                for (int q = 0; q < 4; q++) acc[mt][nt][q] = 0.f;

        #pragma unroll
        for (int ks = 0; ks < 7; ks++) {
            uint32_t a[2][4], b[4][2];
            #pragma unroll
            for (int mt = 0; mt < 2; mt++) {
                int r0 = mbase + 16 * mt + gid;
                int k0 = 16 * ks + 2 * ctid;
                a[mt][0] = *(const uint32_t*)&xs[r0 * XS_H + k0];
                a[mt][1] = *(const uint32_t*)&xs[(r0 + 8) * XS_H + k0];
                a[mt][2] = *(const uint32_t*)&xs[r0 * XS_H + k0 + 8];
                a[mt][3] = *(const uint32_t*)&xs[(r0 + 8) * XS_H + k0 + 8];
            }
            #pragma unroll
            for (int nt = 0; nt < 4; nt++) {
                int n  = nbase + 8 * nt + gid;
                int k0 = 16 * ks + 2 * ctid;
                b[nt][0] = *(const uint32_t*)&w1s[n * W1_H + k0];
                b[nt][1] = *(const uint32_t*)&w1s[n * W1_H + k0 + 8];
            }
            #pragma unroll
            for (int mt = 0; mt < 2; mt++)
                #pragma unroll
                for (int nt = 0; nt < 4; nt++)
                    mma_f16(acc[mt][nt], a[mt], b[nt]);
        }
        __syncthreads();   // all warps done reading xs before h overwrites it

        // ---- epilogue 1: bias + relu -> h halves (aliases xs) ----
        __half* h = xs;    // [128][HS_H]
        #pragma unroll
        for (int mt = 0; mt < 2; mt++) {
            int r0 = mbase + 16 * mt + gid;
            #pragma unroll
            for (int nt = 0; nt < 4; nt++) {
                int c = nbase + 8 * nt + 2 * ctid;
                float bx = b1s[c], by = b1s[c + 1];
                *(uint32_t*)&h[r0 * HS_H + c] =
                    f2_to_h2(fmaxf(acc[mt][nt][0] + bx, 0.f),
                             fmaxf(acc[mt][nt][1] + by, 0.f));
                *(uint32_t*)&h[(r0 + 8) * HS_H + c] =
                    f2_to_h2(fmaxf(acc[mt][nt][2] + bx, 0.f),
                             fmaxf(acc[mt][nt][3] + by, 0.f));
            }
        }
        __syncthreads();

        // ================= GEMM2: [128x64] @ [64x32], B in registers =================
        float acc2[2][2][4];
        #pragma unroll
        for (int mt = 0; mt < 2; mt++)
            #pragma unroll
            for (int nt = 0; nt < 2; nt++)
                #pragma unroll
                for (int q = 0; q < 4; q++) acc2[mt][nt][q] = 0.f;

        #pragma unroll
        for (int ks = 0; ks < 4; ks++) {
            uint32_t a[2][4];
            #pragma unroll
            for (int mt = 0; mt < 2; mt++) {
                int r0 = mbase + 16 * mt + gid;
                int k0 = 16 * ks + 2 * ctid;
                a[mt][0] = *(const uint32_t*)&h[r0 * HS_H + k0];
                a[mt][1] = *(const uint32_t*)&h[(r0 + 8) * HS_H + k0];
                a[mt][2] = *(const uint32_t*)&h[r0 * HS_H + k0 + 8];
                a[mt][3] = *(const uint32_t*)&h[(r0 + 8) * HS_H + k0 + 8];
            }
            #pragma unroll
            for (int mt = 0; mt < 2; mt++)
                #pragma unroll
                for (int nt = 0; nt < 2; nt++)
                    mma_f16(acc2[mt][nt], a[mt], w2r[ks][nt]);
        }

        // ---- epilogue 2: bias + store to gmem ----
        #pragma unroll
        for (int mt = 0; mt < 2; mt++) {
            int r0 = mbase + 16 * mt + gid;
            #pragma unroll
            for (int nt = 0; nt < 2; nt++) {
                int c = nb2 + 8 * nt + 2 * ctid;
                int e = e0 + r0;
                float bx = b2s[c], by = b2s[c + 1];
                if (e < E) {
                    float2 v; v.x = acc2[mt][nt][0] + bx; v.y = acc2[mt][nt][1] + by;
                    *(float2*)&out[(size_t)e * 32 + c] = v;
                }
                if (e + 8 < E) {
                    float2 v; v.x = acc2[mt][nt][2] + bx; v.y = acc2[mt][nt][3] + by;
                    *(float2*)&out[(size_t)(e + 8) * 32 + c] = v;
                }
            }
        }
        __syncthreads();   // before next tile's staging overwrites xs/h
    }
}

extern "C" void kernel_launch(void* const* d_in, const int* in_sizes, int n_in,
                              void* d_out, int out_size) {
    const float* src   = (const float*)d_in[0];
    const float* dst   = (const float*)d_in[1];
    const float* ea    = (const float*)d_in[2];
    const float* u     = (const float*)d_in[3];
    const int*   batch = (const int*)d_in[4];
    const float* W1    = (const float*)d_in[5];
    const float* b1    = (const float*)d_in[6];
    const float* W2    = (const float*)d_in[7];
    const float* b2    = (const float*)d_in[8];
    float*       out   = (float*)d_out;

    int E = in_sizes[0] / 32;
    int ntiles = (E + TILE - 1) / TILE;
    int grid = (ntiles + TPC - 1) / TPC;

    cudaFuncSetAttribute(edge_mlp_h,
                         cudaFuncAttributeMaxDynamicSharedMemorySize, SM_BYTES);
    edge_mlp_h<<<grid, THREADS, SM_BYTES>>>(src, dst, ea, u, batch,
                                            W1, b1, W2, b2, out, E, ntiles);
}